// round 1
// baseline (speedup 1.0000x reference)
#include <cuda_runtime.h>
#include <math.h>

constexpr int B = 4, T = 4096, S = 4096, E = 16;
constexpr int NH = 16, H = 4, MDNH = 16, FFNH = 64;
constexpr int MD = 256, FF = 1024, OUT = 16;
constexpr int NTOK = B * T;

// Scratch (static device allocations — no cudaMalloc allowed)
__device__ int   g_idx[NTOK * NH];                 // 1 MB
__device__ float g_oflat[(size_t)NTOK * MD];       // 16.8 MB
__device__ float g_h1[(size_t)NTOK * FF];          // 67 MB

__device__ __forceinline__ float gelu_exact(float x) { return x * normcdff(x); }

// ---------------------------------------------------------------------------
// K1: 16-nearest-neighbor selection. One thread per target point.
// Stable (ascending dist2, ties -> lower index first) to match jax.lax.top_k.
// ---------------------------------------------------------------------------
__global__ __launch_bounds__(256) void knn_kernel(const float* __restrict__ ct,
                                                  const float* __restrict__ cs) {
    __shared__ float2 scs[S];  // 32 KB
    const int b = blockIdx.y;
    const float* csb = cs + (size_t)b * S * 2;
    for (int i = threadIdx.x; i < S; i += 256)
        scs[i] = make_float2(csb[2 * i], csb[2 * i + 1]);
    __syncthreads();

    const int t = blockIdx.x * 256 + threadIdx.x;
    const float tx = ct[((size_t)b * T + t) * 2 + 0];
    const float ty = ct[((size_t)b * T + t) * 2 + 1];

    float bd[NH];
    int   bi[NH];
#pragma unroll
    for (int i = 0; i < NH; i++) { bd[i] = 3.4e38f; bi[i] = 0; }
    float worst = 3.4e38f;

#pragma unroll 4
    for (int s = 0; s < S; s++) {
        float2 c = scs[s];
        float dx = tx - c.x, dy = ty - c.y;
        float d2 = fmaf(dy, dy, dx * dx);
        if (d2 < worst) {
            int j = NH - 1;
            while (j > 0 && bd[j - 1] > d2) {       // strict > : stable on ties
                bd[j] = bd[j - 1]; bi[j] = bi[j - 1]; --j;
            }
            bd[j] = d2; bi[j] = s;
            worst = bd[NH - 1];
        }
    }
    const int base = (b * T + t) * NH;
#pragma unroll
    for (int i = 0; i < NH; i++) g_idx[base + i] = bi[i];
}

// ---------------------------------------------------------------------------
// K2: per-token local pipeline. One warp per token; all 32 lanes run with
// i = lane & 15 (upper half duplicates; keeps shfl masks full / convergent).
// ---------------------------------------------------------------------------
constexpr int O_PEW1 = 0;      // 2*64
constexpr int O_PEB1 = 128;    // 64
constexpr int O_PEW2 = 192;    // 64*16  (16B aligned)
constexpr int O_PEB2 = 1216;   // 16
constexpr int O_LNG  = 1232;   // 16
constexpr int O_LNB  = 1248;   // 16
constexpr int O_QW   = 1264;   // 256 (16B aligned)
constexpr int O_KW   = 1520;   // 256
constexpr int O_VW   = 1776;   // 256
constexpr int O_OW   = 2032;   // 256
constexpr int O_MW1  = 2288;   // 16*64
constexpr int O_MB1  = 3312;   // 64
constexpr int O_MW2  = 3376;   // 64
constexpr int O_MB2  = 3440;   // 1
constexpr int O_SC   = 3441;   // 4
constexpr int SM_TOT = 3448;

__device__ __forceinline__ void mat16(const float* __restrict__ Wsh,
                                      const float* __restrict__ vin,
                                      float* __restrict__ vout) {
#pragma unroll
    for (int k = 0; k < 16; k++) {
        const float hv = vin[k];
#pragma unroll
        for (int dq = 0; dq < 4; dq++) {
            float4 w = *reinterpret_cast<const float4*>(Wsh + k * 16 + dq * 4);
            vout[dq * 4 + 0] = fmaf(hv, w.x, vout[dq * 4 + 0]);
            vout[dq * 4 + 1] = fmaf(hv, w.y, vout[dq * 4 + 1]);
            vout[dq * 4 + 2] = fmaf(hv, w.z, vout[dq * 4 + 2]);
            vout[dq * 4 + 3] = fmaf(hv, w.w, vout[dq * 4 + 3]);
        }
    }
}

__global__ __launch_bounds__(256) void token_kernel(
    const float* __restrict__ x, const float* __restrict__ ct, const float* __restrict__ cs,
    const float* __restrict__ pe_w1, const float* __restrict__ pe_b1,
    const float* __restrict__ pe_w2, const float* __restrict__ pe_b2,
    const float* __restrict__ ln_g, const float* __restrict__ ln_b,
    const float* __restrict__ q_w, const float* __restrict__ k_w,
    const float* __restrict__ v_w, const float* __restrict__ lscale,
    const float* __restrict__ out_w,
    const float* __restrict__ mnh_w1, const float* __restrict__ mnh_b1,
    const float* __restrict__ mnh_w2, const float* __restrict__ mnh_b2) {
    __shared__ float sm[SM_TOT];
    const int tid = threadIdx.x;
    for (int i = tid; i < 128;  i += 256) sm[O_PEW1 + i] = pe_w1[i];
    for (int i = tid; i < 64;   i += 256) sm[O_PEB1 + i] = pe_b1[i];
    for (int i = tid; i < 1024; i += 256) sm[O_PEW2 + i] = pe_w2[i];
    for (int i = tid; i < 16;   i += 256) sm[O_PEB2 + i] = pe_b2[i];
    for (int i = tid; i < 16;   i += 256) sm[O_LNG + i]  = ln_g[i];
    for (int i = tid; i < 16;   i += 256) sm[O_LNB + i]  = ln_b[i];
    for (int i = tid; i < 256;  i += 256) sm[O_QW + i]   = q_w[i];
    for (int i = tid; i < 256;  i += 256) sm[O_KW + i]   = k_w[i];
    for (int i = tid; i < 256;  i += 256) sm[O_VW + i]   = v_w[i];
    for (int i = tid; i < 256;  i += 256) sm[O_OW + i]   = out_w[i];
    for (int i = tid; i < 1024; i += 256) sm[O_MW1 + i]  = mnh_w1[i];
    for (int i = tid; i < 64;   i += 256) sm[O_MB1 + i]  = mnh_b1[i];
    for (int i = tid; i < 64;   i += 256) sm[O_MW2 + i]  = mnh_w2[i];
    if (tid == 0) sm[O_MB2] = mnh_b2[0];
    if (tid < 4)  sm[O_SC + tid] = expf(fminf(lscale[tid], 4.6051702f));
    __syncthreads();

    const int warp = blockIdx.x * 8 + (tid >> 5);   // token id
    const int lane = tid & 31;
    const int i    = lane & 15;                     // neighbor slot
    const int b    = warp / T;
    const int nidx = g_idx[warp * NH + i];

    // gather x_nh[i][:]
    float xr[16];
    const float4* xrow = reinterpret_cast<const float4*>(x + ((size_t)b * S + nidx) * E);
#pragma unroll
    for (int q4 = 0; q4 < 4; q4++) {
        float4 v4 = __ldg(xrow + q4);
        xr[q4 * 4 + 0] = v4.x; xr[q4 * 4 + 1] = v4.y;
        xr[q4 * 4 + 2] = v4.z; xr[q4 * 4 + 3] = v4.w;
    }
    const float2 scoord = __ldg(reinterpret_cast<const float2*>(cs) + (size_t)b * S + nidx);
    const float2 tcoord = __ldg(reinterpret_cast<const float2*>(ct) + warp);
    const float c0 = scoord.x - tcoord.x, c1 = scoord.y - tcoord.y;

    // positional-embedding MLP -> h
    float h[16];
#pragma unroll
    for (int d = 0; d < 16; d++) h[d] = sm[O_PEB2 + d];
#pragma unroll
    for (int j = 0; j < FFNH; j++) {
        float z = fmaf(c0, sm[O_PEW1 + j], fmaf(c1, sm[O_PEW1 + 64 + j], sm[O_PEB1 + j]));
        z = gelu_exact(z);
#pragma unroll
        for (int dq = 0; dq < 4; dq++) {
            float4 w = *reinterpret_cast<const float4*>(sm + O_PEW2 + j * 16 + dq * 4);
            h[dq * 4 + 0] = fmaf(z, w.x, h[dq * 4 + 0]);
            h[dq * 4 + 1] = fmaf(z, w.y, h[dq * 4 + 1]);
            h[dq * 4 + 2] = fmaf(z, w.z, h[dq * 4 + 2]);
            h[dq * 4 + 3] = fmaf(z, w.w, h[dq * 4 + 3]);
        }
    }

    // residual + LayerNorm (population variance, eps 1e-5)
    float mu = 0.f;
#pragma unroll
    for (int d = 0; d < 16; d++) { h[d] += xr[d]; mu += h[d]; }
    mu *= (1.f / 16.f);
    float var = 0.f;
#pragma unroll
    for (int d = 0; d < 16; d++) { float c = h[d] - mu; var = fmaf(c, c, var); }
    var *= (1.f / 16.f);
    const float rstd = 1.f / sqrtf(var + 1e-5f);
#pragma unroll
    for (int d = 0; d < 16; d++)
        h[d] = (h[d] - mu) * rstd * sm[O_LNG + d] + sm[O_LNB + d];

    // q/k/v projections
    float q[16], k[16], v[16];
#pragma unroll
    for (int d = 0; d < 16; d++) { q[d] = 0.f; k[d] = 0.f; v[d] = 0.f; }
    mat16(sm + O_QW, h, q);
    mat16(sm + O_KW, h, k);
    mat16(sm + O_VW, xr, v);

    // cosine attention per head (HD=4), neighbor j via warp shuffle
    float o[16];
#pragma unroll
    for (int hh = 0; hh < H; hh++) {
        float qh[4], kh[4], vh[4];
#pragma unroll
        for (int c = 0; c < 4; c++) {
            qh[c] = q[hh * 4 + c]; kh[c] = k[hh * 4 + c]; vh[c] = v[hh * 4 + c];
        }
        float qs = fmaf(qh[3], qh[3], fmaf(qh[2], qh[2], fmaf(qh[1], qh[1], qh[0] * qh[0])));
        float ks = fmaf(kh[3], kh[3], fmaf(kh[2], kh[2], fmaf(kh[1], kh[1], kh[0] * kh[0])));
        const float qi = 1.f / (sqrtf(qs) + 1e-6f);
        const float ki = 1.f / (sqrtf(ks) + 1e-6f);
#pragma unroll
        for (int c = 0; c < 4; c++) { qh[c] *= qi; kh[c] *= ki; }

        const float scl = sm[O_SC + hh];
        float lg[16];
#pragma unroll
        for (int j = 0; j < 16; j++) {
            float dot = 0.f;
#pragma unroll
            for (int c = 0; c < 4; c++) {
                float kj = __shfl_sync(0xffffffffu, kh[c], j);
                dot = fmaf(qh[c], kj, dot);
            }
            lg[j] = dot * scl;
        }
        float mx = lg[0];
#pragma unroll
        for (int j = 1; j < 16; j++) mx = fmaxf(mx, lg[j]);
        float ssum = 0.f;
#pragma unroll
        for (int j = 0; j < 16; j++) { lg[j] = expf(lg[j] - mx); ssum += lg[j]; }
        const float inv = 1.f / ssum;
        float oh[4] = {0.f, 0.f, 0.f, 0.f};
#pragma unroll
        for (int j = 0; j < 16; j++) {
            const float a = lg[j] * inv;
#pragma unroll
            for (int c = 0; c < 4; c++) {
                float vj = __shfl_sync(0xffffffffu, vh[c], j);
                oh[c] = fmaf(a, vj, oh[c]);
            }
        }
#pragma unroll
        for (int c = 0; c < 4; c++) o[hh * 4 + c] = oh[c];
    }

    // attention out-projection
    float o2[16];
#pragma unroll
    for (int d = 0; d < 16; d++) o2[d] = 0.f;
    mat16(sm + O_OW, o, o2);

    // per-neighbor MLP (dim 1) + broadcast residual
    float acc2 = 0.f;
#pragma unroll
    for (int j = 0; j < FFNH; j++) {
        float z = sm[O_MB1 + j];
#pragma unroll
        for (int kk = 0; kk < 16; kk++)
            z = fmaf(o2[kk], sm[O_MW1 + kk * 64 + j], z);
        acc2 = fmaf(gelu_exact(z), sm[O_MW2 + j], acc2);
    }
    const float m = gelu_exact(acc2 + sm[O_MB2]);

    if (lane < 16) {
        float4* dst = reinterpret_cast<float4*>(g_oflat + (size_t)warp * MD + i * 16);
#pragma unroll
        for (int dq = 0; dq < 4; dq++)
            dst[dq] = make_float4(o2[dq * 4 + 0] + m, o2[dq * 4 + 1] + m,
                                  o2[dq * 4 + 2] + m, o2[dq * 4 + 3] + m);
    }
}

// ---------------------------------------------------------------------------
// K3: h1 = gelu(o_flat[16384,256] @ mo_w1[256,1024] + b1). Tiled fp32 GEMM.
// ---------------------------------------------------------------------------
constexpr int BM = 64, BN = 64, BK = 16;

__global__ __launch_bounds__(256) void gemm1_kernel(const float* __restrict__ Wb,
                                                    const float* __restrict__ bias) {
    __shared__ float As[BK * 65];   // As[kk][r], padded stride
    __shared__ float Bs[BK * BN];
    const int tid = threadIdx.x;
    const int row0 = blockIdx.y * BM;
    const int col0 = blockIdx.x * BN;
    const int tx = tid & 15, ty = tid >> 4;

    float acc[4][4];
#pragma unroll
    for (int a = 0; a < 4; a++)
#pragma unroll
        for (int c = 0; c < 4; c++) acc[a][c] = 0.f;

    const int ar  = tid >> 2;        // 0..63
    const int akq = tid & 3;         // 0..3
    const int bkk = tid >> 4;        // 0..15
    const int bc4 = (tid & 15) * 4;

    for (int kt = 0; kt < MD; kt += BK) {
        float4 av = *reinterpret_cast<const float4*>(
            g_oflat + (size_t)(row0 + ar) * MD + kt + akq * 4);
        float4 bv = *reinterpret_cast<const float4*>(
            Wb + (size_t)(kt + bkk) * FF + col0 + bc4);
        As[(akq * 4 + 0) * 65 + ar] = av.x;
        As[(akq * 4 + 1) * 65 + ar] = av.y;
        As[(akq * 4 + 2) * 65 + ar] = av.z;
        As[(akq * 4 + 3) * 65 + ar] = av.w;
        *reinterpret_cast<float4*>(Bs + bkk * BN + bc4) = bv;
        __syncthreads();
#pragma unroll
        for (int kk = 0; kk < BK; kk++) {
            const float a0 = As[kk * 65 + ty * 4 + 0];
            const float a1 = As[kk * 65 + ty * 4 + 1];
            const float a2 = As[kk * 65 + ty * 4 + 2];
            const float a3 = As[kk * 65 + ty * 4 + 3];
            const float4 bb = *reinterpret_cast<const float4*>(Bs + kk * BN + tx * 4);
            acc[0][0] = fmaf(a0, bb.x, acc[0][0]); acc[0][1] = fmaf(a0, bb.y, acc[0][1]);
            acc[0][2] = fmaf(a0, bb.z, acc[0][2]); acc[0][3] = fmaf(a0, bb.w, acc[0][3]);
            acc[1][0] = fmaf(a1, bb.x, acc[1][0]); acc[1][1] = fmaf(a1, bb.y, acc[1][1]);
            acc[1][2] = fmaf(a1, bb.z, acc[1][2]); acc[1][3] = fmaf(a1, bb.w, acc[1][3]);
            acc[2][0] = fmaf(a2, bb.x, acc[2][0]); acc[2][1] = fmaf(a2, bb.y, acc[2][1]);
            acc[2][2] = fmaf(a2, bb.z, acc[2][2]); acc[2][3] = fmaf(a2, bb.w, acc[2][3]);
            acc[3][0] = fmaf(a3, bb.x, acc[3][0]); acc[3][1] = fmaf(a3, bb.y, acc[3][1]);
            acc[3][2] = fmaf(a3, bb.z, acc[3][2]); acc[3][3] = fmaf(a3, bb.w, acc[3][3]);
        }
        __syncthreads();
    }

    const float4 bsv = *reinterpret_cast<const float4*>(bias + col0 + tx * 4);
#pragma unroll
    for (int a = 0; a < 4; a++) {
        const int row = row0 + ty * 4 + a;
        float4 outv;
        outv.x = gelu_exact(acc[a][0] + bsv.x);
        outv.y = gelu_exact(acc[a][1] + bsv.y);
        outv.z = gelu_exact(acc[a][2] + bsv.z);
        outv.w = gelu_exact(acc[a][3] + bsv.w);
        *reinterpret_cast<float4*>(g_h1 + (size_t)row * FF + col0 + tx * 4) = outv;
    }
}

// ---------------------------------------------------------------------------
// K4: out = gelu(h1[16384,1024] @ mo_w2[1024,16] + b2). Thread per (tok, n).
// ---------------------------------------------------------------------------
__global__ __launch_bounds__(256) void mlp2_kernel(const float* __restrict__ W2,
                                                   const float* __restrict__ b2,
                                                   float* __restrict__ out) {
    const int gid = blockIdx.x * 256 + threadIdx.x;
    const int tok = gid >> 4;
    const int n   = gid & 15;
    const float* hrow = g_h1 + (size_t)tok * FF;
    float acc = b2[n];
#pragma unroll 8
    for (int kk = 0; kk < FF; kk++)
        acc = fmaf(__ldg(hrow + kk), __ldg(W2 + kk * 16 + n), acc);
    out[(size_t)tok * 16 + n] = gelu_exact(acc);
}

// ---------------------------------------------------------------------------
extern "C" void kernel_launch(void* const* d_in, const int* in_sizes, int n_in,
                              void* d_out, int out_size) {
    const float* x      = (const float*)d_in[0];
    const float* ct     = (const float*)d_in[1];
    const float* cs     = (const float*)d_in[2];
    const float* pe_w1  = (const float*)d_in[3];
    const float* pe_b1  = (const float*)d_in[4];
    const float* pe_w2  = (const float*)d_in[5];
    const float* pe_b2  = (const float*)d_in[6];
    const float* ln_g   = (const float*)d_in[7];
    const float* ln_b   = (const float*)d_in[8];
    const float* q_w    = (const float*)d_in[9];
    const float* k_w    = (const float*)d_in[10];
    const float* v_w    = (const float*)d_in[11];
    const float* ls     = (const float*)d_in[12];
    const float* out_w  = (const float*)d_in[13];
    const float* mnh_w1 = (const float*)d_in[14];
    const float* mnh_b1 = (const float*)d_in[15];
    const float* mnh_w2 = (const float*)d_in[16];
    const float* mnh_b2 = (const float*)d_in[17];
    const float* mo_w1  = (const float*)d_in[18];
    const float* mo_b1  = (const float*)d_in[19];
    const float* mo_w2  = (const float*)d_in[20];
    const float* mo_b2  = (const float*)d_in[21];

    knn_kernel<<<dim3(T / 256, B), 256>>>(ct, cs);
    token_kernel<<<NTOK / 8, 256>>>(x, ct, cs, pe_w1, pe_b1, pe_w2, pe_b2,
                                    ln_g, ln_b, q_w, k_w, v_w, ls, out_w,
                                    mnh_w1, mnh_b1, mnh_w2, mnh_b2);
    gemm1_kernel<<<dim3(FF / BN, NTOK / BM), 256>>>(mo_w1, mo_b1);
    mlp2_kernel<<<NTOK * OUT / 256, 256>>>(mo_w2, mo_b2, (float*)d_out);
}

// round 2
// speedup vs baseline: 5.5317x; 5.5317x over previous
#include <cuda_runtime.h>
#include <math.h>

constexpr int B = 4, T = 4096, S = 4096, E = 16;
constexpr int NH = 16, H = 4, MDNH = 16, FFNH = 64;
constexpr int MD = 256, FF = 1024, OUT = 16;
constexpr int NTOK = B * T;

// Scratch (static device allocations — no cudaMalloc allowed)
__device__ int   g_idx[NTOK * NH];                 // 1 MB
__device__ float g_oflat[(size_t)NTOK * MD];       // 16.8 MB
__device__ float g_h1[(size_t)NTOK * FF];          // 67 MB

__device__ __forceinline__ float gelu_exact(float x) { return x * normcdff(x); }

// ---------------------------------------------------------------------------
// K1: 16-nearest-neighbor selection. One thread per target point.
// Register-resident sorted list; insertion is fully predicated (no dynamic
// indexing -> no local memory). Stable: ascending dist2, ties keep lower
// source index first (matches jax.lax.top_k).
// ---------------------------------------------------------------------------
__global__ __launch_bounds__(64) void knn_kernel(const float* __restrict__ ct,
                                                 const float* __restrict__ cs) {
    __shared__ float2 scs[S];  // 32 KB
    const int b = blockIdx.y;
    const float* csb = cs + (size_t)b * S * 2;
    for (int i = threadIdx.x; i < S; i += 64)
        scs[i] = make_float2(csb[2 * i], csb[2 * i + 1]);
    __syncthreads();

    const int t = blockIdx.x * 64 + threadIdx.x;
    const float tx = ct[((size_t)b * T + t) * 2 + 0];
    const float ty = ct[((size_t)b * T + t) * 2 + 1];

    float bd[NH];
    int   bi[NH];
#pragma unroll
    for (int i = 0; i < NH; i++) { bd[i] = 3.4e38f; bi[i] = 0; }
    float worst = 3.4e38f;

#pragma unroll 4
    for (int s = 0; s < S; s++) {
        float2 c = scs[s];
        float dx = tx - c.x, dy = ty - c.y;
        float d2 = fmaf(dy, dy, dx * dx);
        if (d2 < worst) {
            // predicated register insertion: carry (cd,ci) down the list.
            // First displacement uses strict < (ties keep earlier index);
            // once displaced, keep shifting (flag), preserving duplicates.
            float cd = d2; int ci = s;
            bool ins = false;
#pragma unroll
            for (int j = 0; j < NH; j++) {
                bool sm = ins | (cd < bd[j]);
                float td = bd[j]; int ti = bi[j];
                bd[j] = sm ? cd : td;
                bi[j] = sm ? ci : ti;
                cd = sm ? td : cd;
                ci = sm ? ti : ci;
                ins = sm;
            }
            worst = bd[NH - 1];
        }
    }
    const int base = (b * T + t) * NH;
#pragma unroll
    for (int i = 0; i < NH; i++) g_idx[base + i] = bi[i];
}

// ---------------------------------------------------------------------------
// K2: per-token local pipeline. 16 lanes per token (2 tokens per warp),
// neighbor exchange via width-16 shuffles. All 32 lanes useful.
// ---------------------------------------------------------------------------
constexpr int O_PEW1 = 0;      // 2*64
constexpr int O_PEB1 = 128;    // 64
constexpr int O_PEW2 = 192;    // 64*16  (16B aligned)
constexpr int O_PEB2 = 1216;   // 16
constexpr int O_LNG  = 1232;   // 16
constexpr int O_LNB  = 1248;   // 16
constexpr int O_QW   = 1264;   // 256 (16B aligned)
constexpr int O_KW   = 1520;   // 256
constexpr int O_VW   = 1776;   // 256
constexpr int O_OW   = 2032;   // 256
constexpr int O_MW1  = 2288;   // 16*64
constexpr int O_MB1  = 3312;   // 64
constexpr int O_MW2  = 3376;   // 64
constexpr int O_MB2  = 3440;   // 1
constexpr int O_SC   = 3441;   // 4
constexpr int SM_TOT = 3448;

__device__ __forceinline__ void mat16(const float* __restrict__ Wsh,
                                      const float* __restrict__ vin,
                                      float* __restrict__ vout) {
#pragma unroll
    for (int k = 0; k < 16; k++) {
        const float hv = vin[k];
#pragma unroll
        for (int dq = 0; dq < 4; dq++) {
            float4 w = *reinterpret_cast<const float4*>(Wsh + k * 16 + dq * 4);
            vout[dq * 4 + 0] = fmaf(hv, w.x, vout[dq * 4 + 0]);
            vout[dq * 4 + 1] = fmaf(hv, w.y, vout[dq * 4 + 1]);
            vout[dq * 4 + 2] = fmaf(hv, w.z, vout[dq * 4 + 2]);
            vout[dq * 4 + 3] = fmaf(hv, w.w, vout[dq * 4 + 3]);
        }
    }
}

__global__ __launch_bounds__(256) void token_kernel(
    const float* __restrict__ x, const float* __restrict__ ct, const float* __restrict__ cs,
    const float* __restrict__ pe_w1, const float* __restrict__ pe_b1,
    const float* __restrict__ pe_w2, const float* __restrict__ pe_b2,
    const float* __restrict__ ln_g, const float* __restrict__ ln_b,
    const float* __restrict__ q_w, const float* __restrict__ k_w,
    const float* __restrict__ v_w, const float* __restrict__ lscale,
    const float* __restrict__ out_w,
    const float* __restrict__ mnh_w1, const float* __restrict__ mnh_b1,
    const float* __restrict__ mnh_w2, const float* __restrict__ mnh_b2) {
    __shared__ float sm[SM_TOT];
    const int tid = threadIdx.x;
    for (int i = tid; i < 128;  i += 256) sm[O_PEW1 + i] = pe_w1[i];
    for (int i = tid; i < 64;   i += 256) sm[O_PEB1 + i] = pe_b1[i];
    for (int i = tid; i < 1024; i += 256) sm[O_PEW2 + i] = pe_w2[i];
    for (int i = tid; i < 16;   i += 256) sm[O_PEB2 + i] = pe_b2[i];
    for (int i = tid; i < 16;   i += 256) sm[O_LNG + i]  = ln_g[i];
    for (int i = tid; i < 16;   i += 256) sm[O_LNB + i]  = ln_b[i];
    for (int i = tid; i < 256;  i += 256) sm[O_QW + i]   = q_w[i];
    for (int i = tid; i < 256;  i += 256) sm[O_KW + i]   = k_w[i];
    for (int i = tid; i < 256;  i += 256) sm[O_VW + i]   = v_w[i];
    for (int i = tid; i < 256;  i += 256) sm[O_OW + i]   = out_w[i];
    for (int i = tid; i < 1024; i += 256) sm[O_MW1 + i]  = mnh_w1[i];
    for (int i = tid; i < 64;   i += 256) sm[O_MB1 + i]  = mnh_b1[i];
    for (int i = tid; i < 64;   i += 256) sm[O_MW2 + i]  = mnh_w2[i];
    if (tid == 0) sm[O_MB2] = mnh_b2[0];
    if (tid < 4)  sm[O_SC + tid] = expf(fminf(lscale[tid], 4.6051702f));
    __syncthreads();

    const int tok = blockIdx.x * 16 + (tid >> 4);   // token id (16 lanes each)
    const int i   = tid & 15;                       // neighbor slot
    const int b   = tok / T;
    const int nidx = g_idx[tok * NH + i];

    // gather x_nh[i][:]
    float xr[16];
    const float4* xrow = reinterpret_cast<const float4*>(x + ((size_t)b * S + nidx) * E);
#pragma unroll
    for (int q4 = 0; q4 < 4; q4++) {
        float4 v4 = __ldg(xrow + q4);
        xr[q4 * 4 + 0] = v4.x; xr[q4 * 4 + 1] = v4.y;
        xr[q4 * 4 + 2] = v4.z; xr[q4 * 4 + 3] = v4.w;
    }
    const float2 scoord = __ldg(reinterpret_cast<const float2*>(cs) + (size_t)b * S + nidx);
    const float2 tcoord = __ldg(reinterpret_cast<const float2*>(ct) + tok);
    const float c0 = scoord.x - tcoord.x, c1 = scoord.y - tcoord.y;

    // positional-embedding MLP -> h
    float h[16];
#pragma unroll
    for (int d = 0; d < 16; d++) h[d] = sm[O_PEB2 + d];
#pragma unroll
    for (int j = 0; j < FFNH; j++) {
        float z = fmaf(c0, sm[O_PEW1 + j], fmaf(c1, sm[O_PEW1 + 64 + j], sm[O_PEB1 + j]));
        z = gelu_exact(z);
#pragma unroll
        for (int dq = 0; dq < 4; dq++) {
            float4 w = *reinterpret_cast<const float4*>(sm + O_PEW2 + j * 16 + dq * 4);
            h[dq * 4 + 0] = fmaf(z, w.x, h[dq * 4 + 0]);
            h[dq * 4 + 1] = fmaf(z, w.y, h[dq * 4 + 1]);
            h[dq * 4 + 2] = fmaf(z, w.z, h[dq * 4 + 2]);
            h[dq * 4 + 3] = fmaf(z, w.w, h[dq * 4 + 3]);
        }
    }

    // residual + LayerNorm (population variance, eps 1e-5)
    float mu = 0.f;
#pragma unroll
    for (int d = 0; d < 16; d++) { h[d] += xr[d]; mu += h[d]; }
    mu *= (1.f / 16.f);
    float var = 0.f;
#pragma unroll
    for (int d = 0; d < 16; d++) { float c = h[d] - mu; var = fmaf(c, c, var); }
    var *= (1.f / 16.f);
    const float rstd = 1.f / sqrtf(var + 1e-5f);
#pragma unroll
    for (int d = 0; d < 16; d++)
        h[d] = (h[d] - mu) * rstd * sm[O_LNG + d] + sm[O_LNB + d];

    // q/k/v projections
    float q[16], k[16], v[16];
#pragma unroll
    for (int d = 0; d < 16; d++) { q[d] = 0.f; k[d] = 0.f; v[d] = 0.f; }
    mat16(sm + O_QW, h, q);
    mat16(sm + O_KW, h, k);
    mat16(sm + O_VW, xr, v);

    // cosine attention per head (HD=4); neighbor j via width-16 shuffles
    float o[16];
#pragma unroll
    for (int hh = 0; hh < H; hh++) {
        float qh[4], kh[4], vh[4];
#pragma unroll
        for (int c = 0; c < 4; c++) {
            qh[c] = q[hh * 4 + c]; kh[c] = k[hh * 4 + c]; vh[c] = v[hh * 4 + c];
        }
        float qs = fmaf(qh[3], qh[3], fmaf(qh[2], qh[2], fmaf(qh[1], qh[1], qh[0] * qh[0])));
        float ks = fmaf(kh[3], kh[3], fmaf(kh[2], kh[2], fmaf(kh[1], kh[1], kh[0] * kh[0])));
        const float qi = 1.f / (sqrtf(qs) + 1e-6f);
        const float ki = 1.f / (sqrtf(ks) + 1e-6f);
#pragma unroll
        for (int c = 0; c < 4; c++) { qh[c] *= qi; kh[c] *= ki; }

        const float scl = sm[O_SC + hh];
        float lg[16];
#pragma unroll
        for (int j = 0; j < 16; j++) {
            float dot = 0.f;
#pragma unroll
            for (int c = 0; c < 4; c++) {
                float kj = __shfl_sync(0xffffffffu, kh[c], j, 16);
                dot = fmaf(qh[c], kj, dot);
            }
            lg[j] = dot * scl;
        }
        float mx = lg[0];
#pragma unroll
        for (int j = 1; j < 16; j++) mx = fmaxf(mx, lg[j]);
        float ssum = 0.f;
#pragma unroll
        for (int j = 0; j < 16; j++) { lg[j] = expf(lg[j] - mx); ssum += lg[j]; }
        const float inv = 1.f / ssum;
        float oh[4] = {0.f, 0.f, 0.f, 0.f};
#pragma unroll
        for (int j = 0; j < 16; j++) {
            const float a = lg[j] * inv;
#pragma unroll
            for (int c = 0; c < 4; c++) {
                float vj = __shfl_sync(0xffffffffu, vh[c], j, 16);
                oh[c] = fmaf(a, vj, oh[c]);
            }
        }
#pragma unroll
        for (int c = 0; c < 4; c++) o[hh * 4 + c] = oh[c];
    }

    // attention out-projection
    float o2[16];
#pragma unroll
    for (int d = 0; d < 16; d++) o2[d] = 0.f;
    mat16(sm + O_OW, o, o2);

    // per-neighbor MLP (dim 1) + broadcast residual
    float acc2 = 0.f;
#pragma unroll
    for (int j = 0; j < FFNH; j++) {
        float z = sm[O_MB1 + j];
#pragma unroll
        for (int kk = 0; kk < 16; kk++)
            z = fmaf(o2[kk], sm[O_MW1 + kk * 64 + j], z);
        acc2 = fmaf(gelu_exact(z), sm[O_MW2 + j], acc2);
    }
    const float m = gelu_exact(acc2 + sm[O_MB2]);

    float4* dst = reinterpret_cast<float4*>(g_oflat + (size_t)tok * MD + i * 16);
#pragma unroll
    for (int dq = 0; dq < 4; dq++)
        dst[dq] = make_float4(o2[dq * 4 + 0] + m, o2[dq * 4 + 1] + m,
                              o2[dq * 4 + 2] + m, o2[dq * 4 + 3] + m);
}

// ---------------------------------------------------------------------------
// K3: h1 = gelu(o_flat[16384,256] @ mo_w1[256,1024] + b1). Tiled fp32 GEMM.
// ---------------------------------------------------------------------------
constexpr int BM = 64, BN = 64, BK = 16;

__global__ __launch_bounds__(256) void gemm1_kernel(const float* __restrict__ Wb,
                                                    const float* __restrict__ bias) {
    __shared__ float As[BK * 65];   // As[kk][r], padded stride
    __shared__ float Bs[BK * BN];
    const int tid = threadIdx.x;
    const int row0 = blockIdx.y * BM;
    const int col0 = blockIdx.x * BN;
    const int tx = tid & 15, ty = tid >> 4;

    float acc[4][4];
#pragma unroll
    for (int a = 0; a < 4; a++)
#pragma unroll
        for (int c = 0; c < 4; c++) acc[a][c] = 0.f;

    const int ar  = tid >> 2;        // 0..63
    const int akq = tid & 3;         // 0..3
    const int bkk = tid >> 4;        // 0..15
    const int bc4 = (tid & 15) * 4;

    for (int kt = 0; kt < MD; kt += BK) {
        float4 av = *reinterpret_cast<const float4*>(
            g_oflat + (size_t)(row0 + ar) * MD + kt + akq * 4);
        float4 bv = *reinterpret_cast<const float4*>(
            Wb + (size_t)(kt + bkk) * FF + col0 + bc4);
        As[(akq * 4 + 0) * 65 + ar] = av.x;
        As[(akq * 4 + 1) * 65 + ar] = av.y;
        As[(akq * 4 + 2) * 65 + ar] = av.z;
        As[(akq * 4 + 3) * 65 + ar] = av.w;
        *reinterpret_cast<float4*>(Bs + bkk * BN + bc4) = bv;
        __syncthreads();
#pragma unroll
        for (int kk = 0; kk < BK; kk++) {
            const float a0 = As[kk * 65 + ty * 4 + 0];
            const float a1 = As[kk * 65 + ty * 4 + 1];
            const float a2 = As[kk * 65 + ty * 4 + 2];
            const float a3 = As[kk * 65 + ty * 4 + 3];
            const float4 bb = *reinterpret_cast<const float4*>(Bs + kk * BN + tx * 4);
            acc[0][0] = fmaf(a0, bb.x, acc[0][0]); acc[0][1] = fmaf(a0, bb.y, acc[0][1]);
            acc[0][2] = fmaf(a0, bb.z, acc[0][2]); acc[0][3] = fmaf(a0, bb.w, acc[0][3]);
            acc[1][0] = fmaf(a1, bb.x, acc[1][0]); acc[1][1] = fmaf(a1, bb.y, acc[1][1]);
            acc[1][2] = fmaf(a1, bb.z, acc[1][2]); acc[1][3] = fmaf(a1, bb.w, acc[1][3]);
            acc[2][0] = fmaf(a2, bb.x, acc[2][0]); acc[2][1] = fmaf(a2, bb.y, acc[2][1]);
            acc[2][2] = fmaf(a2, bb.z, acc[2][2]); acc[2][3] = fmaf(a2, bb.w, acc[2][3]);
            acc[3][0] = fmaf(a3, bb.x, acc[3][0]); acc[3][1] = fmaf(a3, bb.y, acc[3][1]);
            acc[3][2] = fmaf(a3, bb.z, acc[3][2]); acc[3][3] = fmaf(a3, bb.w, acc[3][3]);
        }
        __syncthreads();
    }

    const float4 bsv = *reinterpret_cast<const float4*>(bias + col0 + tx * 4);
#pragma unroll
    for (int a = 0; a < 4; a++) {
        const int row = row0 + ty * 4 + a;
        float4 outv;
        outv.x = gelu_exact(acc[a][0] + bsv.x);
        outv.y = gelu_exact(acc[a][1] + bsv.y);
        outv.z = gelu_exact(acc[a][2] + bsv.z);
        outv.w = gelu_exact(acc[a][3] + bsv.w);
        *reinterpret_cast<float4*>(g_h1 + (size_t)row * FF + col0 + tx * 4) = outv;
    }
}

// ---------------------------------------------------------------------------
// K4: out = gelu(h1[16384,1024] @ mo_w2[1024,16] + b2). Thread per (tok, n).
// ---------------------------------------------------------------------------
__global__ __launch_bounds__(256) void mlp2_kernel(const float* __restrict__ W2,
                                                   const float* __restrict__ b2,
                                                   float* __restrict__ out) {
    const int gid = blockIdx.x * 256 + threadIdx.x;
    const int tok = gid >> 4;
    const int n   = gid & 15;
    const float* hrow = g_h1 + (size_t)tok * FF;
    float acc = b2[n];
#pragma unroll 8
    for (int kk = 0; kk < FF; kk++)
        acc = fmaf(__ldg(hrow + kk), __ldg(W2 + kk * 16 + n), acc);
    out[(size_t)tok * 16 + n] = gelu_exact(acc);
}

// ---------------------------------------------------------------------------
extern "C" void kernel_launch(void* const* d_in, const int* in_sizes, int n_in,
                              void* d_out, int out_size) {
    const float* x      = (const float*)d_in[0];
    const float* ct     = (const float*)d_in[1];
    const float* cs     = (const float*)d_in[2];
    const float* pe_w1  = (const float*)d_in[3];
    const float* pe_b1  = (const float*)d_in[4];
    const float* pe_w2  = (const float*)d_in[5];
    const float* pe_b2  = (const float*)d_in[6];
    const float* ln_g   = (const float*)d_in[7];
    const float* ln_b   = (const float*)d_in[8];
    const float* q_w    = (const float*)d_in[9];
    const float* k_w    = (const float*)d_in[10];
    const float* v_w    = (const float*)d_in[11];
    const float* ls     = (const float*)d_in[12];
    const float* out_w  = (const float*)d_in[13];
    const float* mnh_w1 = (const float*)d_in[14];
    const float* mnh_b1 = (const float*)d_in[15];
    const float* mnh_w2 = (const float*)d_in[16];
    const float* mnh_b2 = (const float*)d_in[17];
    const float* mo_w1  = (const float*)d_in[18];
    const float* mo_b1  = (const float*)d_in[19];
    const float* mo_w2  = (const float*)d_in[20];
    const float* mo_b2  = (const float*)d_in[21];

    knn_kernel<<<dim3(T / 64, B), 64>>>(ct, cs);
    token_kernel<<<NTOK / 16, 256>>>(x, ct, cs, pe_w1, pe_b1, pe_w2, pe_b2,
                                     ln_g, ln_b, q_w, k_w, v_w, ls, out_w,
                                     mnh_w1, mnh_b1, mnh_w2, mnh_b2);
    gemm1_kernel<<<dim3(FF / BN, NTOK / BM), 256>>>(mo_w1, mo_b1);
    mlp2_kernel<<<NTOK * OUT / 256, 256>>>(mo_w2, mo_b2, (float*)d_out);
}